// round 15
// baseline (speedup 1.0000x reference)
#include <cuda_runtime.h>
#include <cstdint>

// Problem constants (fixed by the dataset)
#define LQ_   256
#define HH_   2
#define HQ_   32
#define DD_   128
#define SS_   16
#define BS_   64
#define GG_   16
#define NB_   64                           // Lkv / BS
#define ZSPLIT 2
#define S_PER  (SS_ / ZSPLIT)              // 8 blocks per CTA
#define SM_SCALE 0.08838834764831845f      // 1/sqrt(128)

// Packed KV scratch: fragment-native float2 pairs, PRE-ROUNDED to tf32 (rna).
// kpack[h][nb][ub:8][kt:16][p:4][ul:8]  .x=rna(K[ub*8+ul][kt*8+p])  .y=.. p+4
// vpack[h][nb][db:16][kt:8][p:4][dl:8]  .x=rna(V[kt*8+p][db*8+dl])  .y=.. p+4
__device__ float2 g_kpack[HH_ * NB_ * 4096];
__device__ float2 g_vpack[HH_ * NB_ * 4096];

// Shared memory (float offsets). Row pitches !≡ 0 mod 128B for ldmatrix.
#define QSH_OFF  0
#define QS_STR   132                       // 16 rows x 132 (rna(Q*scale))
#define PSH_OFF  (QSH_OFF + 16*132)        // 2112 ; double-buffered 2x16x68
#define PS_STR   68
#define WS_OFF   (PSH_OFF + 2*16*68)       // 4288
#define IDX_OFF  (WS_OFF + 256)            // 4544
#define SMEM_FLOATS (IDX_OFF + 16)
#define SMEM_BYTES  (SMEM_FLOATS * 4)      // 18,240 B

__device__ __forceinline__ unsigned smem_u32(const void* p) {
    return (unsigned)__cvta_generic_to_shared(p);
}

__device__ __forceinline__ void ldsm_x4(unsigned& r0, unsigned& r1,
                                        unsigned& r2, unsigned& r3, unsigned addr) {
    asm volatile("ldmatrix.sync.aligned.m8n8.x4.shared.b16 {%0,%1,%2,%3}, [%4];"
                 : "=r"(r0), "=r"(r1), "=r"(r2), "=r"(r3) : "r"(addr));
}

__device__ __forceinline__ void mma_tf32(float c[4],
                                         unsigned a0, unsigned a1, unsigned a2, unsigned a3,
                                         unsigned b0, unsigned b1) {
    asm volatile("mma.sync.aligned.m16n8k8.row.col.f32.tf32.tf32.f32 "
                 "{%0,%1,%2,%3}, {%4,%5,%6,%7}, {%8,%9}, {%0,%1,%2,%3};"
                 : "+f"(c[0]), "+f"(c[1]), "+f"(c[2]), "+f"(c[3])
                 : "r"(a0), "r"(a1), "r"(a2), "r"(a3), "r"(b0), "r"(b1));
}

__device__ __forceinline__ unsigned tf32_hi(unsigned x) {
    unsigned r;
    asm("cvt.rna.tf32.f32 %0, %1;" : "=r"(r) : "r"(x));
    return r;
}
__device__ __forceinline__ unsigned fu(float x) { return __float_as_uint(x); }
__device__ __forceinline__ float rna_f(float x) {
    return __uint_as_float(tf32_hi(__float_as_uint(x)));
}

// ---------------------------------------------------------------------------
// Prepass: pack K and V (tf32-rna) into fragment-native float2 tiles,
// AND zero the output buffer (needed by the atomicAdd epilogue).
// ---------------------------------------------------------------------------
__global__ void __launch_bounds__(128)
pack_kv_kernel(const float* __restrict__ k, const float* __restrict__ v,
               float4* __restrict__ out_zero)
{
    const int nb = blockIdx.x, h = blockIdx.y;
    const float* kb = k + ((size_t)nb * BS_ * HH_ + h) * DD_;
    const float* vb = v + ((size_t)nb * BS_ * HH_ + h) * DD_;
    float2* kout = g_kpack + ((size_t)h * NB_ + nb) * 4096;
    float2* vout = g_vpack + ((size_t)h * NB_ + nb) * 4096;

    // Zero out slice: 262,144 float4 total / 128 CTAs = 2048 per CTA.
    {
        const int cta = blockIdx.y * NB_ + blockIdx.x;     // 0..127
        float4* dst = out_zero + (size_t)cta * 2048;
        #pragma unroll
        for (int i = 0; i < 16; i++)
            dst[threadIdx.x + i * 128] = make_float4(0.f, 0.f, 0.f, 0.f);
    }

    // K: pos = ((ub*16 + kt)*4 + p)*8 + ul
    for (int pos = threadIdx.x; pos < 4096; pos += 128) {
        int ul = pos & 7, p = (pos >> 3) & 3, kt = (pos >> 5) & 15, ub = pos >> 9;
        int u = ub * 8 + ul, d = kt * 8 + p;
        kout[pos] = make_float2(rna_f(kb[(size_t)u * (HH_ * DD_) + d]),
                                rna_f(kb[(size_t)u * (HH_ * DD_) + d + 4]));
    }
    // V: pos = ((db*8 + kt)*4 + p)*8 + dl
    for (int pos = threadIdx.x; pos < 4096; pos += 128) {
        int dl = pos & 7, p = (pos >> 3) & 3, kt = (pos >> 5) & 7, db = pos >> 8;
        int d = db * 8 + dl, u = kt * 8 + p;
        vout[pos] = make_float2(rna_f(vb[(size_t)u * (HH_ * DD_) + d]),
                                rna_f(vb[(size_t)(u + 4) * (HH_ * DD_) + d]));
    }
}

// ---------------------------------------------------------------------------
// Main kernel: grid (LQ, HH, ZSPLIT); CTA z handles s in [z*S_PER, (z+1)*S_PER)
// ---------------------------------------------------------------------------
__global__ void __launch_bounds__(128, 5)
hsa_prefill_kernel(const float* __restrict__ q, const float* __restrict__ w,
                   const int* __restrict__ bi, float* __restrict__ out)
{
    extern __shared__ float sm[];
    const int lq   = blockIdx.x;
    const int h    = blockIdx.y;
    const int s0   = blockIdx.z * S_PER;
    const int tid  = threadIdx.x;
    const int warp = tid >> 5;
    const int lane = tid & 31;
    const int gID  = lane >> 2;   // 0..7
    const int tig  = lane & 3;    // 0..3

    // ---- Load Q tile [16][128]; store rna(Q * SM_SCALE).
    {
        const float* qb = q + ((size_t)lq * HQ_ + (size_t)h * GG_) * DD_;
        #pragma unroll
        for (int i = tid; i < (GG_ * DD_) / 4; i += 128) {
            int idx = i * 4;
            int g = idx >> 7, d = idx & 127;
            float4 val = *(const float4*)(qb + idx);
            *(uint4*)(sm + QSH_OFF + g * QS_STR + d) =
                make_uint4(tf32_hi(fu(val.x * SM_SCALE)),
                           tf32_hi(fu(val.y * SM_SCALE)),
                           tf32_hi(fu(val.z * SM_SCALE)),
                           tf32_hi(fu(val.w * SM_SCALE)));
        }
        const float* wb = w + ((size_t)lq * HQ_ + (size_t)h * GG_) * SS_;
        for (int i = tid; i < GG_ * SS_; i += 128) sm[WS_OFF + i] = wb[i];
        if (tid < S_PER)
            ((int*)(sm + IDX_OFF))[tid] =
                bi[((size_t)lq * HH_ + h) * SS_ + s0 + tid];
    }
    __syncthreads();

    // Persistent O accumulators
    float oh[4][4];
    #pragma unroll
    for (int i = 0; i < 4; i++)
        #pragma unroll
        for (int j = 0; j < 4; j++) oh[i][j] = 0.f;

    // ldmatrix A-fragment address components
    const int lr = lane & 7;
    const int lt = lane >> 3;
    const int a_row = lr + ((lt & 1) << 3);
    const int a_col = (lt >> 1) << 2;

    // Per-lane packed-tile offsets (float2 units)
    const int lane_off = tig * 8 + gID;
    const float2* kp_base = g_kpack + (size_t)h * NB_ * 4096
                          + (warp * 2) * 512 + lane_off;
    const float2* vp_base = g_vpack + (size_t)h * NB_ * 4096
                          + (warp * 4) * 256 + lane_off;

    for (int si = 0; si < S_PER; si++) {
        const int blk = ((const int*)(sm + IDX_OFF))[si];  // uniform across CTA
        float* psh = sm + PSH_OFF + (si & 1) * (16 * PS_STR);

        if (blk >= 0) {
            const float2* kp = kp_base + (size_t)blk * 4096;

            // ---- Scores S[16][64] = rna(Q*scale) @ K̃^T
            float cm[2][4] = {{0.f,0.f,0.f,0.f},{0.f,0.f,0.f,0.f}};
            #pragma unroll
            for (int kt = 0; kt < 16; kt++) {
                unsigned a0, a1, a2, a3;
                ldsm_x4(a0, a1, a2, a3,
                        smem_u32(sm + QSH_OFF + a_row * QS_STR + a_col + kt * 8));
                float2 k0 = kp[kt * 32];          // n-tile u0 = warp*16
                float2 k1 = kp[512 + kt * 32];    // n-tile u0 = warp*16 + 8
                mma_tf32(cm[0], a0, a1, a2, a3, fu(k0.x), fu(k0.y));
                mma_tf32(cm[1], a0, a1, a2, a3, fu(k1.x), fu(k1.y));
            }
            // Spill scores (already scaled via Q) into PSH scratch
            #pragma unroll
            for (int nt = 0; nt < 2; nt++) {
                const int u = (warp * 2 + nt) * 8 + tig * 2;
                *(float2*)(psh + gID * PS_STR + u) =
                    make_float2(cm[nt][0], cm[nt][1]);
                *(float2*)(psh + (gID + 8) * PS_STR + u) =
                    make_float2(cm[nt][2], cm[nt][3]);
            }
            __syncthreads();

            // ---- Softmax over 64 keys; fold w[g][s]/sum; write rna(P).
            {
                const int g = tid >> 3, j = tid & 7;
                float vals[8];
                #pragma unroll
                for (int m = 0; m < 8; m++) vals[m] = psh[g * PS_STR + j + m * 8];
                float mx = vals[0];
                #pragma unroll
                for (int m = 1; m < 8; m++) mx = fmaxf(mx, vals[m]);
                mx = fmaxf(mx, __shfl_xor_sync(0xffffffffu, mx, 1));
                mx = fmaxf(mx, __shfl_xor_sync(0xffffffffu, mx, 2));
                mx = fmaxf(mx, __shfl_xor_sync(0xffffffffu, mx, 4));
                float sum = 0.f;
                #pragma unroll
                for (int m = 0; m < 8; m++) { vals[m] = __expf(vals[m] - mx); sum += vals[m]; }
                sum += __shfl_xor_sync(0xffffffffu, sum, 1);
                sum += __shfl_xor_sync(0xffffffffu, sum, 2);
                sum += __shfl_xor_sync(0xffffffffu, sum, 4);
                const float coef = sm[WS_OFF + g * SS_ + s0 + si] / sum;
                #pragma unroll
                for (int m = 0; m < 8; m++)
                    psh[g * PS_STR + j + m * 8] = rna_f(vals[m] * coef);
            }
            __syncthreads();

            // ---- O[16][128] += rna(P) @ Ṽ   (V via 4 independent LDG.64/kt)
            const float2* vp = vp_base + (size_t)blk * 4096;
            #pragma unroll
            for (int kt = 0; kt < 8; kt++) {
                unsigned a0, a1, a2, a3;
                ldsm_x4(a0, a1, a2, a3,
                        smem_u32(psh + a_row * PS_STR + a_col + kt * 8));
                #pragma unroll
                for (int nt = 0; nt < 4; nt++) {
                    float2 vv = vp[nt * 256 + kt * 32];
                    mma_tf32(oh[nt], a0, a1, a2, a3, fu(vv.x), fu(vv.y));
                }
            }
            // No end barrier: next iteration uses the OTHER P buffer.
        }
    }

    // ---- Accumulate partial O (2 CTAs per (lq,h) -> RED.ADD.F32, no return)
    float* ob = out + ((size_t)lq * HQ_ + (size_t)h * GG_) * DD_;
    #pragma unroll
    for (int nt = 0; nt < 4; nt++) {
        const int d = warp * 32 + nt * 8 + tig * 2;
        atomicAdd(ob + (size_t)gID * DD_ + d,           oh[nt][0]);
        atomicAdd(ob + (size_t)gID * DD_ + d + 1,       oh[nt][1]);
        atomicAdd(ob + (size_t)(gID + 8) * DD_ + d,     oh[nt][2]);
        atomicAdd(ob + (size_t)(gID + 8) * DD_ + d + 1, oh[nt][3]);
    }
}

extern "C" void kernel_launch(void* const* d_in, const int* in_sizes, int n_in,
                              void* d_out, int out_size)
{
    const float* q  = (const float*)d_in[0];
    const float* k  = (const float*)d_in[1];
    const float* v  = (const float*)d_in[2];
    const float* w  = (const float*)d_in[3];
    const int*   bi = (const int*)d_in[4];
    float* out = (float*)d_out;

    pack_kv_kernel<<<dim3(NB_, HH_), 128>>>(k, v, (float4*)out);

    cudaFuncSetAttribute(hsa_prefill_kernel,
                         cudaFuncAttributeMaxDynamicSharedMemorySize, SMEM_BYTES);
    hsa_prefill_kernel<<<dim3(LQ_, HH_, ZSPLIT), 128, SMEM_BYTES>>>(q, w, bi, out);
}

// round 16
// speedup vs baseline: 1.8304x; 1.8304x over previous
#include <cuda_runtime.h>
#include <cuda_fp16.h>
#include <cstdint>

// Problem constants (fixed by the dataset)
#define LQ_   256
#define HH_   2
#define HQ_   32
#define DD_   128
#define SS_   16
#define BS_   64
#define GG_   16
#define NB_   64                           // Lkv / BS
#define SM_SCALE 0.08838834764831845f      // 1/sqrt(128)

// Packed KV scratch in fp16, fragment-native for mma.m16n8k16:
// kpack[h][nb][wk:4][ck:8][nt:2][lane:32] (uint2):
//   lane(gID=l>>2, tig=l&3): u = wk*16+nt*8+gID, k0 = ck*16+tig*2
//   .x = half2(K[u][k0], K[u][k0+1])   .y = half2(K[u][k0+8], K[u][k0+9])
// vpack[h][nb][wv:4][ck:4][nt:4][lane:32] (uint2):
//   d = wv*32+nt*8+gID, u0 = ck*16+tig*2
//   .x = half2(V[u0][d], V[u0+1][d])   .y = half2(V[u0+8][d], V[u0+9][d])
__device__ uint2 g_kpack[HH_ * NB_ * 2048];
__device__ uint2 g_vpack[HH_ * NB_ * 2048];

// Shared memory (bytes). Row pitches: 16-byte units, !≡ 0 mod 128B.
#define QS_STRH  136                       // Q fp16: 16 rows x 136 halfs (272B)
#define QH_BYTES (16 * QS_STRH * 2)        // 4352
#define PS_STRH  72                        // P fp16: 16 rows x 72 halfs (144B)
#define PH_BYTES (2 * 16 * PS_STRH * 2)    // 4608 (double-buffered)
#define SC_STR   68                        // f32 score scratch: 16 x 68
#define SC_BYTES (16 * SC_STR * 4)         // 4352
#define QH_OFF   0
#define PH_OFF   (QH_OFF + QH_BYTES)       // 4352
#define SC_OFF   (PH_OFF + PH_BYTES)       // 8960
#define WS_OFF   (SC_OFF + SC_BYTES)       // 13312
#define IDX_OFF  (WS_OFF + 1024)           // 14336
#define SMEM_BYTES (IDX_OFF + 64)          // 14,400 B

__device__ __forceinline__ unsigned smem_u32(const void* p) {
    return (unsigned)__cvta_generic_to_shared(p);
}

__device__ __forceinline__ void ldsm_x4(unsigned& r0, unsigned& r1,
                                        unsigned& r2, unsigned& r3, unsigned addr) {
    asm volatile("ldmatrix.sync.aligned.m8n8.x4.shared.b16 {%0,%1,%2,%3}, [%4];"
                 : "=r"(r0), "=r"(r1), "=r"(r2), "=r"(r3) : "r"(addr));
}

__device__ __forceinline__ void mma_f16(float c[4],
                                        unsigned a0, unsigned a1, unsigned a2, unsigned a3,
                                        unsigned b0, unsigned b1) {
    asm volatile("mma.sync.aligned.m16n8k16.row.col.f32.f16.f16.f32 "
                 "{%0,%1,%2,%3}, {%4,%5,%6,%7}, {%8,%9}, {%0,%1,%2,%3};"
                 : "+f"(c[0]), "+f"(c[1]), "+f"(c[2]), "+f"(c[3])
                 : "r"(a0), "r"(a1), "r"(a2), "r"(a3), "r"(b0), "r"(b1));
}

__device__ __forceinline__ unsigned h2u(__half2 h) {
    return *reinterpret_cast<unsigned*>(&h);
}

// ---------------------------------------------------------------------------
// Prepass: pack K and V into fp16 fragment-native uint2 tiles.
// ---------------------------------------------------------------------------
__global__ void __launch_bounds__(128)
pack_kv_kernel(const float* __restrict__ k, const float* __restrict__ v)
{
    const int nb = blockIdx.x, h = blockIdx.y;
    const float* kb = k + ((size_t)nb * BS_ * HH_ + h) * DD_;
    const float* vb = v + ((size_t)nb * BS_ * HH_ + h) * DD_;
    uint2* kout = g_kpack + ((size_t)h * NB_ + nb) * 2048;
    uint2* vout = g_vpack + ((size_t)h * NB_ + nb) * 2048;

    // K: pos = ((wk*8 + ck)*2 + nt)*32 + lane
    for (int pos = threadIdx.x; pos < 2048; pos += 128) {
        int lane = pos & 31, nt = (pos >> 5) & 1, ck = (pos >> 6) & 7, wk = pos >> 9;
        int u = wk * 16 + nt * 8 + (lane >> 2);
        int k0 = ck * 16 + (lane & 3) * 2;
        const float* kr = kb + (size_t)u * (HH_ * DD_);
        kout[pos] = make_uint2(
            h2u(__floats2half2_rn(kr[k0],     kr[k0 + 1])),
            h2u(__floats2half2_rn(kr[k0 + 8], kr[k0 + 9])));
    }
    // V: pos = ((wv*4 + ck)*4 + nt)*32 + lane
    for (int pos = threadIdx.x; pos < 2048; pos += 128) {
        int lane = pos & 31, nt = (pos >> 5) & 3, ck = (pos >> 7) & 3, wv = pos >> 9;
        int d = wv * 32 + nt * 8 + (lane >> 2);
        int u0 = ck * 16 + (lane & 3) * 2;
        vout[pos] = make_uint2(
            h2u(__floats2half2_rn(vb[(size_t)u0 * (HH_ * DD_) + d],
                                  vb[(size_t)(u0 + 1) * (HH_ * DD_) + d])),
            h2u(__floats2half2_rn(vb[(size_t)(u0 + 8) * (HH_ * DD_) + d],
                                  vb[(size_t)(u0 + 9) * (HH_ * DD_) + d])));
    }
}

// ---------------------------------------------------------------------------
// Main kernel
// ---------------------------------------------------------------------------
__global__ void __launch_bounds__(128, 5)
hsa_prefill_kernel(const float* __restrict__ q, const float* __restrict__ w,
                   const int* __restrict__ bi, float* __restrict__ out)
{
    extern __shared__ char smc[];
    __half* qsh = (__half*)(smc + QH_OFF);
    __half* ph  = (__half*)(smc + PH_OFF);
    float*  sc  = (float*)(smc + SC_OFF);
    float*  ws  = (float*)(smc + WS_OFF);
    int*    idx = (int*)(smc + IDX_OFF);

    const int lq   = blockIdx.x;
    const int h    = blockIdx.y;
    const int tid  = threadIdx.x;
    const int warp = tid >> 5;
    const int lane = tid & 31;
    const int gID  = lane >> 2;   // 0..7
    const int tig  = lane & 3;    // 0..3

    // ---- Load Q tile [16][128]; store fp16(Q * SM_SCALE).
    {
        const float* qb = q + ((size_t)lq * HQ_ + (size_t)h * GG_) * DD_;
        #pragma unroll
        for (int i = tid; i < (GG_ * DD_) / 4; i += 128) {
            int id4 = i * 4;
            int g = id4 >> 7, d = id4 & 127;
            float4 val = *(const float4*)(qb + id4);
            uint2 packed = make_uint2(
                h2u(__floats2half2_rn(val.x * SM_SCALE, val.y * SM_SCALE)),
                h2u(__floats2half2_rn(val.z * SM_SCALE, val.w * SM_SCALE)));
            *(uint2*)(qsh + g * QS_STRH + d) = packed;
        }
        const float* wb = w + ((size_t)lq * HQ_ + (size_t)h * GG_) * SS_;
        for (int i = tid; i < GG_ * SS_; i += 128) ws[i] = wb[i];
        if (tid < SS_)
            idx[tid] = bi[((size_t)lq * HH_ + h) * SS_ + tid];
    }
    __syncthreads();

    // Persistent O accumulators
    float oh[4][4];
    #pragma unroll
    for (int i = 0; i < 4; i++)
        #pragma unroll
        for (int j = 0; j < 4; j++) oh[i][j] = 0.f;

    // ldmatrix A-fragment address components (b16 tiles)
    const int lr = lane & 7;
    const int lt = lane >> 3;
    const int a_row  = lr + ((lt & 1) << 3);
    const int a_colh = (lt >> 1) << 3;        // half units (8 halfs = 16B)

    // Per-lane packed-tile base pointers (uint2 units; lane folded in)
    const uint2* kp_base = g_kpack + (size_t)h * NB_ * 2048 + warp * 512 + lane;
    const uint2* vp_base = g_vpack + (size_t)h * NB_ * 2048 + warp * 512 + lane;

    for (int s = 0; s < SS_; s++) {
        const int blk = idx[s];                          // uniform across CTA
        __half* psh = ph + (s & 1) * (16 * PS_STRH);

        if (blk >= 0) {
            const uint2* kp = kp_base + (size_t)blk * 2048;

            // ---- Scores S[16][64] = fp16(Q*scale) @ fp16(K)^T, k16 chunks
            float cm[2][4] = {{0.f,0.f,0.f,0.f},{0.f,0.f,0.f,0.f}};
            #pragma unroll
            for (int ck = 0; ck < 8; ck++) {
                unsigned a0, a1, a2, a3;
                ldsm_x4(a0, a1, a2, a3,
                        smem_u32(qsh + a_row * QS_STRH + a_colh + ck * 16));
                uint2 k0 = kp[ck * 64];           // n-tile u0 = warp*16
                uint2 k1 = kp[ck * 64 + 32];      // n-tile u0 = warp*16 + 8
                mma_f16(cm[0], a0, a1, a2, a3, k0.x, k0.y);
                mma_f16(cm[1], a0, a1, a2, a3, k1.x, k1.y);
            }
            // Spill scores (scaled via Q) into fp32 scratch
            #pragma unroll
            for (int nt = 0; nt < 2; nt++) {
                const int u = (warp * 2 + nt) * 8 + tig * 2;
                *(float2*)(sc + gID * SC_STR + u) =
                    make_float2(cm[nt][0], cm[nt][1]);
                *(float2*)(sc + (gID + 8) * SC_STR + u) =
                    make_float2(cm[nt][2], cm[nt][3]);
            }
            __syncthreads();

            // ---- Softmax over 64 keys; fold w[g][s]/sum; write fp16 P.
            {
                const int g = tid >> 3, j = tid & 7;
                float vals[8];
                #pragma unroll
                for (int m = 0; m < 8; m++) vals[m] = sc[g * SC_STR + j + m * 8];
                float mx = vals[0];
                #pragma unroll
                for (int m = 1; m < 8; m++) mx = fmaxf(mx, vals[m]);
                mx = fmaxf(mx, __shfl_xor_sync(0xffffffffu, mx, 1));
                mx = fmaxf(mx, __shfl_xor_sync(0xffffffffu, mx, 2));
                mx = fmaxf(mx, __shfl_xor_sync(0xffffffffu, mx, 4));
                float sum = 0.f;
                #pragma unroll
                for (int m = 0; m < 8; m++) { vals[m] = __expf(vals[m] - mx); sum += vals[m]; }
                sum += __shfl_xor_sync(0xffffffffu, sum, 1);
                sum += __shfl_xor_sync(0xffffffffu, sum, 2);
                sum += __shfl_xor_sync(0xffffffffu, sum, 4);
                const float coef = ws[g * SS_ + s] / sum;
                #pragma unroll
                for (int m = 0; m < 8; m++)
                    psh[g * PS_STRH + j + m * 8] = __float2half_rn(vals[m] * coef);
            }
            __syncthreads();

            // ---- O[16][128] += fp16(P) @ fp16(V), k16 chunks
            const uint2* vp = vp_base + (size_t)blk * 2048;
            #pragma unroll
            for (int ck = 0; ck < 4; ck++) {
                unsigned a0, a1, a2, a3;
                ldsm_x4(a0, a1, a2, a3,
                        smem_u32(psh + a_row * PS_STRH + a_colh + ck * 16));
                #pragma unroll
                for (int nt = 0; nt < 4; nt++) {
                    uint2 vv = vp[ck * 128 + nt * 32];
                    mma_f16(oh[nt], a0, a1, a2, a3, vv.x, vv.y);
                }
            }
            // No end barrier: next iteration uses the OTHER P buffer, and the
            // score scratch is only re-written after the next pre-softmax
            // barrier has retired all readers.
        }
    }

    // ---- Write O: warp's d-slice, fragment rows gID / gID+8.
    float* ob = out + ((size_t)lq * HQ_ + (size_t)h * GG_) * DD_;
    #pragma unroll
    for (int nt = 0; nt < 4; nt++) {
        const int d = warp * 32 + nt * 8 + tig * 2;
        *(float2*)(ob + (size_t)gID * DD_ + d)       = make_float2(oh[nt][0], oh[nt][1]);
        *(float2*)(ob + (size_t)(gID + 8) * DD_ + d) = make_float2(oh[nt][2], oh[nt][3]);
    }
}

extern "C" void kernel_launch(void* const* d_in, const int* in_sizes, int n_in,
                              void* d_out, int out_size)
{
    const float* q  = (const float*)d_in[0];
    const float* k  = (const float*)d_in[1];
    const float* v  = (const float*)d_in[2];
    const float* w  = (const float*)d_in[3];
    const int*   bi = (const int*)d_in[4];
    float* out = (float*)d_out;

    pack_kv_kernel<<<dim3(NB_, HH_), 128>>>(k, v);

    cudaFuncSetAttribute(hsa_prefill_kernel,
                         cudaFuncAttributeMaxDynamicSharedMemorySize, SMEM_BYTES);
    hsa_prefill_kernel<<<dim3(LQ_, HH_), 128, SMEM_BYTES>>>(q, w, bi, out);
}

// round 17
// speedup vs baseline: 1.9307x; 1.0548x over previous
#include <cuda_runtime.h>
#include <cuda_fp16.h>
#include <cstdint>

// Problem constants (fixed by the dataset)
#define LQ_   256
#define HH_   2
#define HQ_   32
#define DD_   128
#define SS_   16
#define BS_   64
#define GG_   16
#define NB_   64                           // Lkv / BS
#define SM_SCALE 0.08838834764831845f      // 1/sqrt(128)

// Packed KV scratch in fp16, fragment-native for mma.m16n8k16 (as R16):
// kpack[h][nb][wk:4][ck:8][nt:2][lane:32] (uint2)
// vpack[h][nb][wv:4][ck:4][nt:4][lane:32] (uint2)
__device__ uint2 g_kpack[HH_ * NB_ * 2048];
__device__ uint2 g_vpack[HH_ * NB_ * 2048];

// Shared memory (bytes). Row pitches: 16B units, !≡ 0 mod 128B.
#define QS_STRH  136                       // Q fp16: 16 rows x 136 halfs
#define QH_BYTES (16 * QS_STRH * 2)        // 4352
#define PS_STRH  72                        // P fp16: 16 rows x 72 halfs
#define PH_BYTES (4 * 16 * PS_STRH * 2)    // 9216 (2 groups x double-buffer)
#define SC_STR   68                        // f32 score scratch: 16 x 68
#define SC_BYTES (2 * 16 * SC_STR * 4)     // 8704 (per group)
#define QH_OFF   0
#define PH_OFF   (QH_OFF + QH_BYTES)       // 4352
#define SC_OFF   (PH_OFF + PH_BYTES)       // 13568
#define WS_OFF   (SC_OFF + SC_BYTES)       // 22272
#define IDX_OFF  (WS_OFF + 1024)           // 23296
#define SMEM_BYTES (IDX_OFF + 64)          // 23,360 B
#define OM_STR   132                       // merge buffer: 16 x 132 f32 (reuses smem front)

__device__ __forceinline__ unsigned smem_u32(const void* p) {
    return (unsigned)__cvta_generic_to_shared(p);
}

__device__ __forceinline__ void ldsm_x4(unsigned& r0, unsigned& r1,
                                        unsigned& r2, unsigned& r3, unsigned addr) {
    asm volatile("ldmatrix.sync.aligned.m8n8.x4.shared.b16 {%0,%1,%2,%3}, [%4];"
                 : "=r"(r0), "=r"(r1), "=r"(r2), "=r"(r3) : "r"(addr));
}

__device__ __forceinline__ void mma_f16(float c[4],
                                        unsigned a0, unsigned a1, unsigned a2, unsigned a3,
                                        unsigned b0, unsigned b1) {
    asm volatile("mma.sync.aligned.m16n8k16.row.col.f32.f16.f16.f32 "
                 "{%0,%1,%2,%3}, {%4,%5,%6,%7}, {%8,%9}, {%0,%1,%2,%3};"
                 : "+f"(c[0]), "+f"(c[1]), "+f"(c[2]), "+f"(c[3])
                 : "r"(a0), "r"(a1), "r"(a2), "r"(a3), "r"(b0), "r"(b1));
}

__device__ __forceinline__ unsigned h2u(__half2 h) {
    return *reinterpret_cast<unsigned*>(&h);
}

#define GROUP_BAR(grp) asm volatile("bar.sync %0, 128;" :: "r"((grp) + 1) : "memory")

// ---------------------------------------------------------------------------
// Prepass: pack K and V into fp16 fragment-native uint2 tiles. 256 CTAs.
// ---------------------------------------------------------------------------
__global__ void __launch_bounds__(256)
pack_kv_kernel(const float* __restrict__ k, const float* __restrict__ v)
{
    const int nb = blockIdx.x, h = blockIdx.y;
    const int p0 = blockIdx.z * 1024, p1 = p0 + 1024;
    const float* kb = k + ((size_t)nb * BS_ * HH_ + h) * DD_;
    const float* vb = v + ((size_t)nb * BS_ * HH_ + h) * DD_;
    uint2* kout = g_kpack + ((size_t)h * NB_ + nb) * 2048;
    uint2* vout = g_vpack + ((size_t)h * NB_ + nb) * 2048;

    // K: pos = ((wk*8 + ck)*2 + nt)*32 + lane
    for (int pos = p0 + threadIdx.x; pos < p1; pos += 256) {
        int lane = pos & 31, nt = (pos >> 5) & 1, ck = (pos >> 6) & 7, wk = pos >> 9;
        int u = wk * 16 + nt * 8 + (lane >> 2);
        int k0 = ck * 16 + (lane & 3) * 2;
        const float* kr = kb + (size_t)u * (HH_ * DD_);
        kout[pos] = make_uint2(
            h2u(__floats2half2_rn(kr[k0],     kr[k0 + 1])),
            h2u(__floats2half2_rn(kr[k0 + 8], kr[k0 + 9])));
    }
    // V: pos = ((wv*4 + ck)*4 + nt)*32 + lane
    for (int pos = p0 + threadIdx.x; pos < p1; pos += 256) {
        int lane = pos & 31, nt = (pos >> 5) & 3, ck = (pos >> 7) & 3, wv = pos >> 9;
        int d = wv * 32 + nt * 8 + (lane >> 2);
        int u0 = ck * 16 + (lane & 3) * 2;
        vout[pos] = make_uint2(
            h2u(__floats2half2_rn(vb[(size_t)u0 * (HH_ * DD_) + d],
                                  vb[(size_t)(u0 + 1) * (HH_ * DD_) + d])),
            h2u(__floats2half2_rn(vb[(size_t)(u0 + 8) * (HH_ * DD_) + d],
                                  vb[(size_t)(u0 + 9) * (HH_ * DD_) + d])));
    }
}

// ---------------------------------------------------------------------------
// Main kernel: 256 threads = 2 groups of 4 warps; group g handles s = 2*si+g.
// ---------------------------------------------------------------------------
__global__ void __launch_bounds__(256, 3)
hsa_prefill_kernel(const float* __restrict__ q, const float* __restrict__ w,
                   const int* __restrict__ bi, float* __restrict__ out)
{
    extern __shared__ char smc[];
    __half* qsh = (__half*)(smc + QH_OFF);
    __half* ph  = (__half*)(smc + PH_OFF);
    float*  scb = (float*)(smc + SC_OFF);
    float*  ws  = (float*)(smc + WS_OFF);
    int*    idx = (int*)(smc + IDX_OFF);

    const int lq    = blockIdx.x;
    const int h     = blockIdx.y;
    const int tid   = threadIdx.x;
    const int warp  = tid >> 5;
    const int lane  = tid & 31;
    const int group = warp >> 2;    // 0 or 1
    const int wg    = warp & 3;     // warp within group
    const int wg_tid = tid & 127;
    const int gID   = lane >> 2;    // 0..7
    const int tig   = lane & 3;     // 0..3

    // ---- Load Q tile [16][128] as fp16(Q*scale); w coefs; indices.
    {
        const float* qb = q + ((size_t)lq * HQ_ + (size_t)h * GG_) * DD_;
        #pragma unroll
        for (int i = tid; i < (GG_ * DD_) / 4; i += 256) {
            int id4 = i * 4;
            int g = id4 >> 7, d = id4 & 127;
            float4 val = *(const float4*)(qb + id4);
            *(uint2*)(qsh + g * QS_STRH + d) = make_uint2(
                h2u(__floats2half2_rn(val.x * SM_SCALE, val.y * SM_SCALE)),
                h2u(__floats2half2_rn(val.z * SM_SCALE, val.w * SM_SCALE)));
        }
        const float* wb = w + ((size_t)lq * HQ_ + (size_t)h * GG_) * SS_;
        for (int i = tid; i < GG_ * SS_; i += 256) ws[i] = wb[i];
        if (tid < SS_)
            idx[tid] = bi[((size_t)lq * HH_ + h) * SS_ + tid];
    }
    __syncthreads();

    // Persistent O accumulators (this group's partial)
    float oh[4][4];
    #pragma unroll
    for (int i = 0; i < 4; i++)
        #pragma unroll
        for (int j = 0; j < 4; j++) oh[i][j] = 0.f;

    // ldmatrix A-fragment address components
    const int lr = lane & 7;
    const int lt = lane >> 3;
    const int a_row  = lr + ((lt & 1) << 3);
    const int a_colh = (lt >> 1) << 3;        // half units

    // Per-lane packed-tile base pointers (wg = warp within group)
    const uint2* kp_base = g_kpack + (size_t)h * NB_ * 2048 + wg * 512 + lane;
    const uint2* vp_base = g_vpack + (size_t)h * NB_ * 2048 + wg * 512 + lane;

    float* sc = scb + group * (16 * SC_STR);

    #pragma unroll 1
    for (int si = 0; si < 8; si++) {
        const int s = si * 2 + group;                    // this group's block
        const int blk = idx[s];                          // uniform within group
        __half* psh = ph + (group * 2 + (si & 1)) * (16 * PS_STRH);

        if (blk >= 0) {
            const uint2* kp = kp_base + (size_t)blk * 2048;

            // ---- Scores S[16][64] = fp16(Q*scale) @ fp16(K)^T
            float cm[2][4] = {{0.f,0.f,0.f,0.f},{0.f,0.f,0.f,0.f}};
            #pragma unroll
            for (int ck = 0; ck < 8; ck++) {
                unsigned a0, a1, a2, a3;
                ldsm_x4(a0, a1, a2, a3,
                        smem_u32(qsh + a_row * QS_STRH + a_colh + ck * 16));
                uint2 k0 = kp[ck * 64];           // n-tile u0 = wg*16
                uint2 k1 = kp[ck * 64 + 32];      // n-tile u0 = wg*16 + 8
                mma_f16(cm[0], a0, a1, a2, a3, k0.x, k0.y);
                mma_f16(cm[1], a0, a1, a2, a3, k1.x, k1.y);
            }
            // Spill scores into this group's fp32 scratch
            #pragma unroll
            for (int nt = 0; nt < 2; nt++) {
                const int u = (wg * 2 + nt) * 8 + tig * 2;
                *(float2*)(sc + gID * SC_STR + u) =
                    make_float2(cm[nt][0], cm[nt][1]);
                *(float2*)(sc + (gID + 8) * SC_STR + u) =
                    make_float2(cm[nt][2], cm[nt][3]);
            }
            GROUP_BAR(group);

            // ---- Softmax over 64 keys; fold w[g][s]/sum; write fp16 P.
            {
                const int g = wg_tid >> 3, j = wg_tid & 7;
                float vals[8];
                #pragma unroll
                for (int m = 0; m < 8; m++) vals[m] = sc[g * SC_STR + j + m * 8];
                float mx = vals[0];
                #pragma unroll
                for (int m = 1; m < 8; m++) mx = fmaxf(mx, vals[m]);
                mx = fmaxf(mx, __shfl_xor_sync(0xffffffffu, mx, 1));
                mx = fmaxf(mx, __shfl_xor_sync(0xffffffffu, mx, 2));
                mx = fmaxf(mx, __shfl_xor_sync(0xffffffffu, mx, 4));
                float sum = 0.f;
                #pragma unroll
                for (int m = 0; m < 8; m++) { vals[m] = __expf(vals[m] - mx); sum += vals[m]; }
                sum += __shfl_xor_sync(0xffffffffu, sum, 1);
                sum += __shfl_xor_sync(0xffffffffu, sum, 2);
                sum += __shfl_xor_sync(0xffffffffu, sum, 4);
                const float coef = ws[g * SS_ + s] / sum;
                #pragma unroll
                for (int m = 0; m < 8; m++)
                    psh[g * PS_STRH + j + m * 8] = __float2half_rn(vals[m] * coef);
            }
            GROUP_BAR(group);

            // ---- O[16][128] += fp16(P) @ fp16(V)
            const uint2* vp = vp_base + (size_t)blk * 2048;
            #pragma unroll
            for (int ck = 0; ck < 4; ck++) {
                unsigned a0, a1, a2, a3;
                ldsm_x4(a0, a1, a2, a3,
                        smem_u32(psh + a_row * PS_STRH + a_colh + ck * 16));
                #pragma unroll
                for (int nt = 0; nt < 4; nt++) {
                    uint2 vv = vp[ck * 128 + nt * 32];
                    mma_f16(oh[nt], a0, a1, a2, a3, vv.x, vv.y);
                }
            }
            // No end barrier: double-buffered P; sc reuse ordered by the next
            // iteration's pre-softmax barrier.
        }
    }

    // ---- Merge: group 1 deposits its partial into smem (reusing the front),
    //      then group 0 adds and writes gmem.
    __syncthreads();                      // everyone done with qsh/ph/sc
    float* om = (float*)smc;              // 16 x OM_STR f32 merge buffer
    if (group == 1) {
        #pragma unroll
        for (int nt = 0; nt < 4; nt++) {
            const int d = wg * 32 + nt * 8 + tig * 2;
            *(float2*)(om + gID * OM_STR + d)       = make_float2(oh[nt][0], oh[nt][1]);
            *(float2*)(om + (gID + 8) * OM_STR + d) = make_float2(oh[nt][2], oh[nt][3]);
        }
    }
    __syncthreads();
    if (group == 0) {
        float* ob = out + ((size_t)lq * HQ_ + (size_t)h * GG_) * DD_;
        #pragma unroll
        for (int nt = 0; nt < 4; nt++) {
            const int d = wg * 32 + nt * 8 + tig * 2;
            float2 m0 = *(float2*)(om + gID * OM_STR + d);
            float2 m1 = *(float2*)(om + (gID + 8) * OM_STR + d);
            *(float2*)(ob + (size_t)gID * DD_ + d) =
                make_float2(oh[nt][0] + m0.x, oh[nt][1] + m0.y);
            *(float2*)(ob + (size_t)(gID + 8) * DD_ + d) =
                make_float2(oh[nt][2] + m1.x, oh[nt][3] + m1.y);
        }
    }
}

extern "C" void kernel_launch(void* const* d_in, const int* in_sizes, int n_in,
                              void* d_out, int out_size)
{
    const float* q  = (const float*)d_in[0];
    const float* k  = (const float*)d_in[1];
    const float* v  = (const float*)d_in[2];
    const float* w  = (const float*)d_in[3];
    const int*   bi = (const int*)d_in[4];
    float* out = (float*)d_out;

    pack_kv_kernel<<<dim3(NB_, HH_, 2), 256>>>(k, v);

    cudaFuncSetAttribute(hsa_prefill_kernel,
                         cudaFuncAttributeMaxDynamicSharedMemorySize, SMEM_BYTES);
    hsa_prefill_kernel<<<dim3(LQ_, HH_), 256, SMEM_BYTES>>>(q, w, bi, out);
}